// round 2
// baseline (speedup 1.0000x reference)
#include <cuda_runtime.h>
#include <math.h>
#include <stdint.h>

// Problem constants
#define BB   2
#define NN   4096
#define DD   2048
#define EE   8
#define CAP  640
#define NTOK (BB * NN)                         // 8192
#define SDISP ((long long)NTOK * EE * CAP)     // 41,943,040 elements per tensor

// ---------------- scratch (device globals; no allocation allowed) ----------
__device__ float g_g0[NTOK], g_g1[NTOK];       // renormalized top-2 gate values
__device__ int   g_i0[NTOK], g_i1[NTOK];       // top-2 expert indices
__device__ int   g_r1[NTOK];                   // slot-1 routed flag
__device__ int   g_pos0[NTOK], g_pos1[NTOK];   // queue positions (INT_MAX if unrouted)
__device__ float g_proxy[BB * EE];             // sum over n of raw_gates
__device__ float g_zsum;                       // sum of lse^2
__device__ int   g_cnt0[BB * EE];              // clipped top-1 counts per (b,e)

__global__ void init_kernel() {
    int t = threadIdx.x;
    if (t < BB * EE) g_proxy[t] = 0.0f;
    if (t == BB * EE) g_zsum = 0.0f;
}

// ---------------- gating: logits GEMV + softmax + top2 + threshold ---------
// grid 256 blocks x 256 threads. Block = 32 tokens. Warp = 4 tokens.
// W (8x2048 f32 = 64KB) cached in dynamic smem; x read once, coalesced float4.
__global__ void gating_kernel(const float* __restrict__ x,
                              const float* __restrict__ W,
                              const float* __restrict__ probs) {
    extern __shared__ float4 Wsm4[];           // 8 * 512 float4 = 64 KB
    __shared__ float proxy_sm[EE];
    __shared__ float z_sm;

    int tid = threadIdx.x;
    if (tid < EE) proxy_sm[tid] = 0.0f;
    if (tid == EE) z_sm = 0.0f;

    const float4* W4 = (const float4*)W;
    for (int i = tid; i < EE * DD / 4; i += 256) Wsm4[i] = W4[i];
    __syncthreads();

    int warp = tid >> 5, lane = tid & 31;
    int tok0 = blockIdx.x * 32 + warp * 4;

    float acc[4][8];
#pragma unroll
    for (int t = 0; t < 4; t++)
#pragma unroll
        for (int e = 0; e < 8; e++) acc[t][e] = 0.0f;

    const float4* xr0 = (const float4*)(x + (size_t)(tok0 + 0) * DD);
    const float4* xr1 = (const float4*)(x + (size_t)(tok0 + 1) * DD);
    const float4* xr2 = (const float4*)(x + (size_t)(tok0 + 2) * DD);
    const float4* xr3 = (const float4*)(x + (size_t)(tok0 + 3) * DD);

#pragma unroll
    for (int j = 0; j < 16; j++) {
        float4 xv0 = xr0[j * 32 + lane];
        float4 xv1 = xr1[j * 32 + lane];
        float4 xv2 = xr2[j * 32 + lane];
        float4 xv3 = xr3[j * 32 + lane];
#pragma unroll
        for (int e = 0; e < 8; e++) {
            float4 wv = Wsm4[e * 512 + j * 32 + lane];
            acc[0][e] += xv0.x * wv.x + xv0.y * wv.y + xv0.z * wv.z + xv0.w * wv.w;
            acc[1][e] += xv1.x * wv.x + xv1.y * wv.y + xv1.z * wv.z + xv1.w * wv.w;
            acc[2][e] += xv2.x * wv.x + xv2.y * wv.y + xv2.z * wv.z + xv2.w * wv.w;
            acc[3][e] += xv3.x * wv.x + xv3.y * wv.y + xv3.z * wv.z + xv3.w * wv.w;
        }
    }

    // cross-lane reduction (butterfly): every lane ends with full sums
#pragma unroll
    for (int off = 16; off > 0; off >>= 1)
#pragma unroll
        for (int t = 0; t < 4; t++)
#pragma unroll
            for (int e = 0; e < 8; e++)
                acc[t][e] += __shfl_xor_sync(0xffffffffu, acc[t][e], off);

    if (lane < 4) {
        float row[8];
#pragma unroll
        for (int e = 0; e < 8; e++)
            row[e] = (lane == 0) ? acc[0][e] : (lane == 1) ? acc[1][e]
                   : (lane == 2) ? acc[2][e] : acc[3][e];

        int tok = tok0 + lane;

        float m = row[0];
#pragma unroll
        for (int e = 1; e < 8; e++) m = fmaxf(m, row[e]);
        float ex[8];
        float s = 0.0f;
#pragma unroll
        for (int e = 0; e < 8; e++) { ex[e] = expf(row[e] - m); s += ex[e]; }
        float inv = 1.0f / s;

        float raw[8];
#pragma unroll
        for (int e = 0; e < 8; e++) raw[e] = ex[e] * inv;

        // top-2 (ties -> lower index, like lax.top_k)
        float gv0 = -1.0f, gv1 = -1.0f;
        int   i0 = 0, i1 = 0;
#pragma unroll
        for (int e = 0; e < 8; e++) {
            float r = raw[e];
            if (r > gv0) { gv1 = gv0; i1 = i0; gv0 = r; i0 = e; }
            else if (r > gv1) { gv1 = r; i1 = e; }
        }

        float denom = fmaxf(gv0 + gv1, 1e-9f);
        float g0r = gv0 / denom;
        float g1r = gv1 / denom;

        // slot0 always routes; slot1: probs[1,b,n] < gates1 / 0.2
        int r1 = probs[NTOK + tok] < (g1r / 0.2f);

        g_g0[tok] = g0r; g_g1[tok] = g1r;
        g_i0[tok] = i0;  g_i1[tok] = i1;
        g_r1[tok] = r1;

        float lse = m + logf(s);
        atomicAdd(&z_sm, lse * lse);
#pragma unroll
        for (int e = 0; e < 8; e++) atomicAdd(&proxy_sm[e], raw[e]);
    }
    __syncthreads();

    int b = blockIdx.x >> 7;   // 128 blocks per batch row
    if (tid < 8) atomicAdd(&g_proxy[b * 8 + tid], proxy_sm[tid]);
    if (tid == 8) atomicAdd(&g_zsum, z_sm);
}

// ---------------- scan: exclusive cumsum per (b, expert), capacity clip ----
// 2 blocks (one per b) x 256 threads, 16 tokens/thread.
__global__ void scan_kernel() {
    __shared__ int hist[EE * 256];
    __shared__ int total_sm[EE];
    __shared__ int cnt0_sm[EE];

    int tid = threadIdx.x;
    int b = blockIdx.x;
    int tbase = b * NN + tid * 16;
    int warp = tid >> 5, lane = tid & 31;

    // ================= slot k = 0 (always routed) =================
#pragma unroll
    for (int e = 0; e < 8; e++) hist[e * 256 + tid] = 0;
    for (int i = 0; i < 16; i++) {
        int e = g_i0[tbase + i];
        hist[e * 256 + tid]++;
    }
    __syncthreads();

    // per-expert exclusive scan over the 256 thread-segments (warp e scans expert e)
    {
        int e = warp;
        int v[8]; int s = 0;
#pragma unroll
        for (int i = 0; i < 8; i++) { v[i] = hist[e * 256 + lane * 8 + i]; s += v[i]; }
        int xs = s;
#pragma unroll
        for (int off = 1; off < 32; off <<= 1) {
            int y = __shfl_up_sync(0xffffffffu, xs, off);
            if (lane >= off) xs += y;
        }
        int run = xs - s;   // exclusive
#pragma unroll
        for (int i = 0; i < 8; i++) { hist[e * 256 + lane * 8 + i] = run; run += v[i]; }
        if (lane == 31) total_sm[e] = xs;
    }
    __syncthreads();

    if (tid < 8) {
        int c = min(total_sm[tid], CAP);
        cnt0_sm[tid] = c;
        g_cnt0[b * 8 + tid] = c;
    }

    for (int i = 0; i < 16; i++) {
        int t = tbase + i;
        int e = g_i0[t];
        int p = hist[e * 256 + tid];
        hist[e * 256 + tid] = p + 1;
        g_pos0[t] = p;
    }
    __syncthreads();

    // ================= slot k = 1 (threshold-routed) =================
#pragma unroll
    for (int e = 0; e < 8; e++) hist[e * 256 + tid] = 0;
    for (int i = 0; i < 16; i++) {
        int t = tbase + i;
        if (g_r1[t]) hist[g_i1[t] * 256 + tid]++;
    }
    __syncthreads();

    {
        int e = warp;
        int v[8]; int s = 0;
#pragma unroll
        for (int i = 0; i < 8; i++) { v[i] = hist[e * 256 + lane * 8 + i]; s += v[i]; }
        int xs = s;
#pragma unroll
        for (int off = 1; off < 32; off <<= 1) {
            int y = __shfl_up_sync(0xffffffffu, xs, off);
            if (lane >= off) xs += y;
        }
        int run = xs - s;
#pragma unroll
        for (int i = 0; i < 8; i++) { hist[e * 256 + lane * 8 + i] = run; run += v[i]; }
    }
    __syncthreads();

    for (int i = 0; i < 16; i++) {
        int t = tbase + i;
        if (g_r1[t]) {
            int e = g_i1[t];
            int p = hist[e * 256 + tid];
            hist[e * 256 + tid] = p + 1;
            g_pos1[t] = cnt0_sm[e] + p;   // offset by clipped top-1 count
        } else {
            g_pos1[t] = 0x7fffffff;
        }
    }
}

// ---------------- scatter nonzeros + scalars (after memset of d_out) -------
// one thread per (token, slot): 16384 threads for better latency hiding
__global__ void scatter_kernel(float* __restrict__ out) {
    int idx = blockIdx.x * blockDim.x + threadIdx.x;
    int tok = idx >> 1;
    int slot = idx & 1;
    if (tok < NTOK) {
        long long tb = (long long)tok * (EE * CAP);
        int p = slot ? g_pos1[tok] : g_pos0[tok];
        if (p < CAP) {
            int e = slot ? g_i1[tok] : g_i0[tok];
            float g = slot ? g_g1[tok] : g_g0[tok];
            long long o = tb + (long long)e * CAP + p;
            out[SDISP + o] = g;                      // combine
            out[o] = (g != 0.0f) ? 1.0f : 0.0f;      // dispatch
        }
    }
    if (blockIdx.x == 0 && threadIdx.x == 0) {
        float bal = 0.0f;
        for (int i = 0; i < BB * EE; i++)
            bal += g_proxy[i] * (float)g_cnt0[i];
        bal = bal * (64.0f / 16.0f) / ((float)NN * (float)NN);
        out[2 * SDISP]     = bal;
        out[2 * SDISP + 1] = g_zsum / (float)NTOK;
    }
}

extern "C" void kernel_launch(void* const* d_in, const int* in_sizes, int n_in,
                              void* d_out, int out_size) {
    const float* x     = (const float*)d_in[0];
    const float* W     = (const float*)d_in[1];
    const float* probs = (const float*)d_in[2];
    float* out = (float*)d_out;

    static cudaStream_t s2 = nullptr;
    static cudaEvent_t ev_fork = nullptr, ev_join = nullptr;
    if (s2 == nullptr) {
        cudaStreamCreateWithFlags(&s2, cudaStreamNonBlocking);
        cudaEventCreateWithFlags(&ev_fork, cudaEventDisableTiming);
        cudaEventCreateWithFlags(&ev_join, cudaEventDisableTiming);
        cudaFuncSetAttribute(gating_kernel,
                             cudaFuncAttributeMaxDynamicSharedMemorySize, 65536);
    }

    // Fork: 336MB zero-fill on s2, concurrent with gating/scan on main stream.
    cudaEventRecord(ev_fork, 0);
    cudaStreamWaitEvent(s2, ev_fork, 0);
    cudaMemsetAsync(d_out, 0, (size_t)out_size * sizeof(float), s2);
    cudaEventRecord(ev_join, s2);

    init_kernel<<<1, 32>>>();
    gating_kernel<<<256, 256, 65536>>>(x, W, probs);
    scan_kernel<<<BB, 256>>>();

    // Join: scatter needs both the zeroed output and the scan results.
    cudaStreamWaitEvent(0, ev_join, 0);
    scatter_kernel<<<2 * NTOK / 256, 256>>>(out);
}

// round 3
// speedup vs baseline: 1.0672x; 1.0672x over previous
#include <cuda_runtime.h>
#include <math.h>
#include <stdint.h>

// Problem constants
#define BB   2
#define NN   4096
#define DD   2048
#define EE   8
#define CAP  640
#define NTOK (BB * NN)                         // 8192
#define SDISP ((long long)NTOK * EE * CAP)     // 41,943,040 elements per tensor

// ---------------- scratch (device globals; no allocation allowed) ----------
__device__ float g_g0[NTOK], g_g1[NTOK];       // renormalized top-2 gate values
__device__ int   g_i0[NTOK], g_i1[NTOK];       // top-2 expert indices
__device__ int   g_r1[NTOK];                   // slot-1 routed flag
__device__ int   g_pos0[NTOK], g_pos1[NTOK];   // queue positions (INT_MAX if unrouted)
__device__ float g_proxy[BB * EE];             // sum over n of raw_gates
__device__ float g_zsum;                       // sum of lse^2
__device__ int   g_cnt0[BB * EE];              // clipped top-1 counts per (b,e)

__global__ void init_kernel() {
    int t = threadIdx.x;
    if (t < BB * EE) g_proxy[t] = 0.0f;
    if (t == BB * EE) g_zsum = 0.0f;
}

// ---------------- gating: logits GEMV + softmax + top2 + threshold ---------
// grid 256 blocks x 256 threads. Block = 32 tokens. Warp = 4 tokens.
// W (8x2048 f32 = 64KB) cached in dynamic smem; x read once, coalesced float4.
__global__ void gating_kernel(const float* __restrict__ x,
                              const float* __restrict__ W,
                              const float* __restrict__ probs) {
    extern __shared__ float4 Wsm4[];           // 8 * 512 float4 = 64 KB
    __shared__ float proxy_sm[EE];
    __shared__ float z_sm;

    int tid = threadIdx.x;
    if (tid < EE) proxy_sm[tid] = 0.0f;
    if (tid == EE) z_sm = 0.0f;

    const float4* W4 = (const float4*)W;
    for (int i = tid; i < EE * DD / 4; i += 256) Wsm4[i] = W4[i];
    __syncthreads();

    int warp = tid >> 5, lane = tid & 31;
    int tok0 = blockIdx.x * 32 + warp * 4;

    float acc[4][8];
#pragma unroll
    for (int t = 0; t < 4; t++)
#pragma unroll
        for (int e = 0; e < 8; e++) acc[t][e] = 0.0f;

    const float4* xr0 = (const float4*)(x + (size_t)(tok0 + 0) * DD);
    const float4* xr1 = (const float4*)(x + (size_t)(tok0 + 1) * DD);
    const float4* xr2 = (const float4*)(x + (size_t)(tok0 + 2) * DD);
    const float4* xr3 = (const float4*)(x + (size_t)(tok0 + 3) * DD);

#pragma unroll
    for (int j = 0; j < 16; j++) {
        float4 xv0 = xr0[j * 32 + lane];
        float4 xv1 = xr1[j * 32 + lane];
        float4 xv2 = xr2[j * 32 + lane];
        float4 xv3 = xr3[j * 32 + lane];
#pragma unroll
        for (int e = 0; e < 8; e++) {
            float4 wv = Wsm4[e * 512 + j * 32 + lane];
            acc[0][e] += xv0.x * wv.x + xv0.y * wv.y + xv0.z * wv.z + xv0.w * wv.w;
            acc[1][e] += xv1.x * wv.x + xv1.y * wv.y + xv1.z * wv.z + xv1.w * wv.w;
            acc[2][e] += xv2.x * wv.x + xv2.y * wv.y + xv2.z * wv.z + xv2.w * wv.w;
            acc[3][e] += xv3.x * wv.x + xv3.y * wv.y + xv3.z * wv.z + xv3.w * wv.w;
        }
    }

    // cross-lane reduction (butterfly): every lane ends with full sums
#pragma unroll
    for (int off = 16; off > 0; off >>= 1)
#pragma unroll
        for (int t = 0; t < 4; t++)
#pragma unroll
            for (int e = 0; e < 8; e++)
                acc[t][e] += __shfl_xor_sync(0xffffffffu, acc[t][e], off);

    if (lane < 4) {
        float row[8];
#pragma unroll
        for (int e = 0; e < 8; e++)
            row[e] = (lane == 0) ? acc[0][e] : (lane == 1) ? acc[1][e]
                   : (lane == 2) ? acc[2][e] : acc[3][e];

        int tok = tok0 + lane;

        float m = row[0];
#pragma unroll
        for (int e = 1; e < 8; e++) m = fmaxf(m, row[e]);
        float ex[8];
        float s = 0.0f;
#pragma unroll
        for (int e = 0; e < 8; e++) { ex[e] = expf(row[e] - m); s += ex[e]; }
        float inv = 1.0f / s;

        float raw[8];
#pragma unroll
        for (int e = 0; e < 8; e++) raw[e] = ex[e] * inv;

        // top-2 (ties -> lower index, like lax.top_k)
        float gv0 = -1.0f, gv1 = -1.0f;
        int   i0 = 0, i1 = 0;
#pragma unroll
        for (int e = 0; e < 8; e++) {
            float r = raw[e];
            if (r > gv0) { gv1 = gv0; i1 = i0; gv0 = r; i0 = e; }
            else if (r > gv1) { gv1 = r; i1 = e; }
        }

        float denom = fmaxf(gv0 + gv1, 1e-9f);
        float g0r = gv0 / denom;
        float g1r = gv1 / denom;

        // slot0 always routes; slot1: probs[1,b,n] < gates1 / 0.2
        int r1 = probs[NTOK + tok] < (g1r / 0.2f);

        g_g0[tok] = g0r; g_g1[tok] = g1r;
        g_i0[tok] = i0;  g_i1[tok] = i1;
        g_r1[tok] = r1;

        float lse = m + logf(s);
        atomicAdd(&z_sm, lse * lse);
#pragma unroll
        for (int e = 0; e < 8; e++) atomicAdd(&proxy_sm[e], raw[e]);
    }
    __syncthreads();

    int b = blockIdx.x >> 7;   // 128 blocks per batch row
    if (tid < 8) atomicAdd(&g_proxy[b * 8 + tid], proxy_sm[tid]);
    if (tid == 8) atomicAdd(&g_zsum, z_sm);
}

// ---------------- scan: exclusive cumsum per (b, expert), capacity clip ----
// 2 blocks (one per b) x 256 threads, 16 tokens/thread.
__global__ void scan_kernel() {
    __shared__ int hist[EE * 256];
    __shared__ int total_sm[EE];
    __shared__ int cnt0_sm[EE];

    int tid = threadIdx.x;
    int b = blockIdx.x;
    int tbase = b * NN + tid * 16;
    int warp = tid >> 5, lane = tid & 31;

    // ================= slot k = 0 (always routed) =================
#pragma unroll
    for (int e = 0; e < 8; e++) hist[e * 256 + tid] = 0;
    for (int i = 0; i < 16; i++) {
        int e = g_i0[tbase + i];
        hist[e * 256 + tid]++;
    }
    __syncthreads();

    // per-expert exclusive scan over the 256 thread-segments (warp e scans expert e)
    {
        int e = warp;
        int v[8]; int s = 0;
#pragma unroll
        for (int i = 0; i < 8; i++) { v[i] = hist[e * 256 + lane * 8 + i]; s += v[i]; }
        int xs = s;
#pragma unroll
        for (int off = 1; off < 32; off <<= 1) {
            int y = __shfl_up_sync(0xffffffffu, xs, off);
            if (lane >= off) xs += y;
        }
        int run = xs - s;   // exclusive
#pragma unroll
        for (int i = 0; i < 8; i++) { hist[e * 256 + lane * 8 + i] = run; run += v[i]; }
        if (lane == 31) total_sm[e] = xs;
    }
    __syncthreads();

    if (tid < 8) {
        int c = min(total_sm[tid], CAP);
        cnt0_sm[tid] = c;
        g_cnt0[b * 8 + tid] = c;
    }

    for (int i = 0; i < 16; i++) {
        int t = tbase + i;
        int e = g_i0[t];
        int p = hist[e * 256 + tid];
        hist[e * 256 + tid] = p + 1;
        g_pos0[t] = p;
    }
    __syncthreads();

    // ================= slot k = 1 (threshold-routed) =================
#pragma unroll
    for (int e = 0; e < 8; e++) hist[e * 256 + tid] = 0;
    for (int i = 0; i < 16; i++) {
        int t = tbase + i;
        if (g_r1[t]) hist[g_i1[t] * 256 + tid]++;
    }
    __syncthreads();

    {
        int e = warp;
        int v[8]; int s = 0;
#pragma unroll
        for (int i = 0; i < 8; i++) { v[i] = hist[e * 256 + lane * 8 + i]; s += v[i]; }
        int xs = s;
#pragma unroll
        for (int off = 1; off < 32; off <<= 1) {
            int y = __shfl_up_sync(0xffffffffu, xs, off);
            if (lane >= off) xs += y;
        }
        int run = xs - s;
#pragma unroll
        for (int i = 0; i < 8; i++) { hist[e * 256 + lane * 8 + i] = run; run += v[i]; }
    }
    __syncthreads();

    for (int i = 0; i < 16; i++) {
        int t = tbase + i;
        if (g_r1[t]) {
            int e = g_i1[t];
            int p = hist[e * 256 + tid];
            hist[e * 256 + tid] = p + 1;
            g_pos1[t] = cnt0_sm[e] + p;   // offset by clipped top-1 count
        } else {
            g_pos1[t] = 0x7fffffff;
        }
    }
}

// ---------------- fused fill: zeros + inject nonzeros in ONE write pass ----
// Block = one token (8 warps). Warp w owns (token, expert=w) row of 640 floats
// in BOTH dispatch and combine. 128-bit streaming stores; values injected
// inline from the scan results — no memset, no second pass.
__global__ void fill_kernel(float* __restrict__ out) {
    int tok  = blockIdx.x;
    int warp = threadIdx.x >> 5;
    int lane = threadIdx.x & 31;

    // token routing info (same for all 8 warps; L1-cached)
    int   p0 = g_pos0[tok], i0 = g_i0[tok];
    int   p1 = g_pos1[tok], i1 = g_i1[tok];
    float v0 = g_g0[tok],   v1 = g_g1[tok];

    long long rowoff = ((long long)tok * EE + warp) * CAP;
    float4* drow = (float4*)(out + rowoff);           // dispatch row
    float4* crow = (float4*)(out + SDISP + rowoff);   // combine row

    bool m0 = (i0 == warp);   // p0 >= CAP can never match a q-window below
    bool m1 = (i1 == warp);   // p1 = INT_MAX if unrouted

#pragma unroll
    for (int r = 0; r < 5; r++) {
        int q  = lane + 32 * r;   // float4 index within the 640-float row
        int cb = q * 4;           // column base
        float4 c = make_float4(0.f, 0.f, 0.f, 0.f);
        if (m0 && p0 >= cb && p0 < cb + 4) ((float*)&c)[p0 - cb] = v0;
        if (m1 && p1 >= cb && p1 < cb + 4) ((float*)&c)[p1 - cb] = v1;
        float4 d;
        d.x = (c.x != 0.f) ? 1.f : 0.f;
        d.y = (c.y != 0.f) ? 1.f : 0.f;
        d.z = (c.z != 0.f) ? 1.f : 0.f;
        d.w = (c.w != 0.f) ? 1.f : 0.f;
        __stcs(&drow[q], d);
        __stcs(&crow[q], c);
    }

    if (blockIdx.x == 0 && threadIdx.x == 0) {
        float bal = 0.0f;
        for (int i = 0; i < BB * EE; i++)
            bal += g_proxy[i] * (float)g_cnt0[i];
        bal = bal * (64.0f / 16.0f) / ((float)NN * (float)NN);
        out[2 * SDISP]     = bal;
        out[2 * SDISP + 1] = g_zsum / (float)NTOK;
    }
}

extern "C" void kernel_launch(void* const* d_in, const int* in_sizes, int n_in,
                              void* d_out, int out_size) {
    const float* x     = (const float*)d_in[0];
    const float* W     = (const float*)d_in[1];
    const float* probs = (const float*)d_in[2];
    float* out = (float*)d_out;

    static bool configured = false;
    if (!configured) {
        configured = true;
        cudaFuncSetAttribute(gating_kernel,
                             cudaFuncAttributeMaxDynamicSharedMemorySize, 65536);
    }

    init_kernel<<<1, 32>>>();
    gating_kernel<<<256, 256, 65536>>>(x, W, probs);
    scan_kernel<<<BB, 256>>>();
    fill_kernel<<<NTOK, 256>>>(out);
}

// round 5
// speedup vs baseline: 1.0841x; 1.0159x over previous
#include <cuda_runtime.h>
#include <math.h>
#include <stdint.h>

// Problem constants
#define BB   2
#define NN   4096
#define DD   2048
#define EE   8
#define CAP  640
#define NTOK (BB * NN)                         // 8192
#define SDISP ((long long)NTOK * EE * CAP)     // 41,943,040 elements per tensor

// ---------------- scratch (device globals; no allocation allowed) ----------
__device__ float g_g0[NTOK], g_g1[NTOK];       // renormalized top-2 gate values
__device__ int   g_i0[NTOK], g_i1[NTOK];       // top-2 expert indices
__device__ int   g_r1[NTOK];                   // slot-1 routed flag
__device__ int   g_pos0[NTOK], g_pos1[NTOK];   // queue positions (INT_MAX if unrouted)
__device__ float g_proxy[BB * EE];             // sum over n of raw_gates
__device__ float g_zsum;                       // sum of lse^2
__device__ int   g_cnt0[BB * EE];              // clipped top-1 counts per (b,e)

__global__ void init_kernel() {
    int t = threadIdx.x;
    if (t < BB * EE) g_proxy[t] = 0.0f;
    if (t == BB * EE) g_zsum = 0.0f;
}

// ---------------- gating: logits GEMV + softmax + top2 + threshold ---------
// grid 256 blocks x 256 threads. Block = 32 tokens. Warp = 4 tokens.
// W (8x2048 f32 = 64KB) cached in dynamic smem; x read once, coalesced float4.
__global__ void gating_kernel(const float* __restrict__ x,
                              const float* __restrict__ W,
                              const float* __restrict__ probs) {
    extern __shared__ float4 Wsm4[];           // 8 * 512 float4 = 64 KB
    __shared__ float proxy_sm[EE];
    __shared__ float z_sm;

    int tid = threadIdx.x;
    if (tid < EE) proxy_sm[tid] = 0.0f;
    if (tid == EE) z_sm = 0.0f;

    const float4* W4 = (const float4*)W;
    for (int i = tid; i < EE * DD / 4; i += 256) Wsm4[i] = W4[i];
    __syncthreads();

    int warp = tid >> 5, lane = tid & 31;
    int tok0 = blockIdx.x * 32 + warp * 4;

    float acc[4][8];
#pragma unroll
    for (int t = 0; t < 4; t++)
#pragma unroll
        for (int e = 0; e < 8; e++) acc[t][e] = 0.0f;

    const float4* xr0 = (const float4*)(x + (size_t)(tok0 + 0) * DD);
    const float4* xr1 = (const float4*)(x + (size_t)(tok0 + 1) * DD);
    const float4* xr2 = (const float4*)(x + (size_t)(tok0 + 2) * DD);
    const float4* xr3 = (const float4*)(x + (size_t)(tok0 + 3) * DD);

#pragma unroll
    for (int j = 0; j < 16; j++) {
        float4 xv0 = xr0[j * 32 + lane];
        float4 xv1 = xr1[j * 32 + lane];
        float4 xv2 = xr2[j * 32 + lane];
        float4 xv3 = xr3[j * 32 + lane];
#pragma unroll
        for (int e = 0; e < 8; e++) {
            float4 wv = Wsm4[e * 512 + j * 32 + lane];
            acc[0][e] += xv0.x * wv.x + xv0.y * wv.y + xv0.z * wv.z + xv0.w * wv.w;
            acc[1][e] += xv1.x * wv.x + xv1.y * wv.y + xv1.z * wv.z + xv1.w * wv.w;
            acc[2][e] += xv2.x * wv.x + xv2.y * wv.y + xv2.z * wv.z + xv2.w * wv.w;
            acc[3][e] += xv3.x * wv.x + xv3.y * wv.y + xv3.z * wv.z + xv3.w * wv.w;
        }
    }

    // cross-lane reduction (butterfly): every lane ends with full sums
#pragma unroll
    for (int off = 16; off > 0; off >>= 1)
#pragma unroll
        for (int t = 0; t < 4; t++)
#pragma unroll
            for (int e = 0; e < 8; e++)
                acc[t][e] += __shfl_xor_sync(0xffffffffu, acc[t][e], off);

    if (lane < 4) {
        float row[8];
#pragma unroll
        for (int e = 0; e < 8; e++)
            row[e] = (lane == 0) ? acc[0][e] : (lane == 1) ? acc[1][e]
                   : (lane == 2) ? acc[2][e] : acc[3][e];

        int tok = tok0 + lane;

        float m = row[0];
#pragma unroll
        for (int e = 1; e < 8; e++) m = fmaxf(m, row[e]);
        float ex[8];
        float s = 0.0f;
#pragma unroll
        for (int e = 0; e < 8; e++) { ex[e] = expf(row[e] - m); s += ex[e]; }
        float inv = 1.0f / s;

        float raw[8];
#pragma unroll
        for (int e = 0; e < 8; e++) raw[e] = ex[e] * inv;

        // top-2 (ties -> lower index, like lax.top_k)
        float gv0 = -1.0f, gv1 = -1.0f;
        int   i0 = 0, i1 = 0;
#pragma unroll
        for (int e = 0; e < 8; e++) {
            float r = raw[e];
            if (r > gv0) { gv1 = gv0; i1 = i0; gv0 = r; i0 = e; }
            else if (r > gv1) { gv1 = r; i1 = e; }
        }

        float denom = fmaxf(gv0 + gv1, 1e-9f);
        float g0r = gv0 / denom;
        float g1r = gv1 / denom;

        // slot0 always routes; slot1: probs[1,b,n] < gates1 / 0.2
        int r1 = probs[NTOK + tok] < (g1r / 0.2f);

        g_g0[tok] = g0r; g_g1[tok] = g1r;
        g_i0[tok] = i0;  g_i1[tok] = i1;
        g_r1[tok] = r1;

        float lse = m + logf(s);
        atomicAdd(&z_sm, lse * lse);
#pragma unroll
        for (int e = 0; e < 8; e++) atomicAdd(&proxy_sm[e], raw[e]);
    }
    __syncthreads();

    int b = blockIdx.x >> 7;   // 128 blocks per batch row
    if (tid < 8) atomicAdd(&g_proxy[b * 8 + tid], proxy_sm[tid]);
    if (tid == 8) atomicAdd(&g_zsum, z_sm);
}

// ---------------- scan: exclusive cumsum per (b, expert), capacity clip ----
// 2 blocks (one per b) x 256 threads, 16 tokens/thread.
__global__ void scan_kernel() {
    __shared__ int hist[EE * 256];
    __shared__ int total_sm[EE];
    __shared__ int cnt0_sm[EE];

    int tid = threadIdx.x;
    int b = blockIdx.x;
    int tbase = b * NN + tid * 16;
    int warp = tid >> 5, lane = tid & 31;

    // ================= slot k = 0 (always routed) =================
#pragma unroll
    for (int e = 0; e < 8; e++) hist[e * 256 + tid] = 0;
    for (int i = 0; i < 16; i++) {
        int e = g_i0[tbase + i];
        hist[e * 256 + tid]++;
    }
    __syncthreads();

    // per-expert exclusive scan over the 256 thread-segments (warp e scans expert e)
    {
        int e = warp;
        int v[8]; int s = 0;
#pragma unroll
        for (int i = 0; i < 8; i++) { v[i] = hist[e * 256 + lane * 8 + i]; s += v[i]; }
        int xs = s;
#pragma unroll
        for (int off = 1; off < 32; off <<= 1) {
            int y = __shfl_up_sync(0xffffffffu, xs, off);
            if (lane >= off) xs += y;
        }
        int run = xs - s;   // exclusive
#pragma unroll
        for (int i = 0; i < 8; i++) { hist[e * 256 + lane * 8 + i] = run; run += v[i]; }
        if (lane == 31) total_sm[e] = xs;
    }
    __syncthreads();

    if (tid < 8) {
        int c = min(total_sm[tid], CAP);
        cnt0_sm[tid] = c;
        g_cnt0[b * 8 + tid] = c;
    }

    for (int i = 0; i < 16; i++) {
        int t = tbase + i;
        int e = g_i0[t];
        int p = hist[e * 256 + tid];
        hist[e * 256 + tid] = p + 1;
        g_pos0[t] = p;
    }
    __syncthreads();

    // ================= slot k = 1 (threshold-routed) =================
#pragma unroll
    for (int e = 0; e < 8; e++) hist[e * 256 + tid] = 0;
    for (int i = 0; i < 16; i++) {
        int t = tbase + i;
        if (g_r1[t]) hist[g_i1[t] * 256 + tid]++;
    }
    __syncthreads();

    {
        int e = warp;
        int v[8]; int s = 0;
#pragma unroll
        for (int i = 0; i < 8; i++) { v[i] = hist[e * 256 + lane * 8 + i]; s += v[i]; }
        int xs = s;
#pragma unroll
        for (int off = 1; off < 32; off <<= 1) {
            int y = __shfl_up_sync(0xffffffffu, xs, off);
            if (lane >= off) xs += y;
        }
        int run = xs - s;
#pragma unroll
        for (int i = 0; i < 8; i++) { hist[e * 256 + lane * 8 + i] = run; run += v[i]; }
    }
    __syncthreads();

    for (int i = 0; i < 16; i++) {
        int t = tbase + i;
        if (g_r1[t]) {
            int e = g_i1[t];
            int p = hist[e * 256 + tid];
            hist[e * 256 + tid] = p + 1;
            g_pos1[t] = cnt0_sm[e] + p;   // offset by clipped top-1 count
        } else {
            g_pos1[t] = 0x7fffffff;
        }
    }
}

// ---------------- fused fill: zeros + inject nonzeros in ONE write pass ----
// Block = one token (8 warps). Warp w owns (token, expert=w) row of 640 floats
// in BOTH dispatch and combine. 128-bit streaming stores; values injected
// inline from the scan results — no memset, no second pass.
__global__ void fill_kernel(float* __restrict__ out) {
    int tok  = blockIdx.x;
    int warp = threadIdx.x >> 5;
    int lane = threadIdx.x & 31;

    // token routing info (same for all 8 warps; L1-cached)
    int   p0 = g_pos0[tok], i0 = g_i0[tok];
    int   p1 = g_pos1[tok], i1 = g_i1[tok];
    float v0 = g_g0[tok],   v1 = g_g1[tok];

    long long rowoff = ((long long)tok * EE + warp) * CAP;
    float4* drow = (float4*)(out + rowoff);           // dispatch row
    float4* crow = (float4*)(out + SDISP + rowoff);   // combine row

    bool m0 = (i0 == warp);   // p0 >= CAP can never match a q-window below
    bool m1 = (i1 == warp);   // p1 = INT_MAX if unrouted

#pragma unroll
    for (int r = 0; r < 5; r++) {
        int q  = lane + 32 * r;   // float4 index within the 640-float row
        int cb = q * 4;           // column base
        float4 c = make_float4(0.f, 0.f, 0.f, 0.f);
        if (m0 && p0 >= cb && p0 < cb + 4) ((float*)&c)[p0 - cb] = v0;
        if (m1 && p1 >= cb && p1 < cb + 4) ((float*)&c)[p1 - cb] = v1;
        float4 d;
        d.x = (c.x != 0.f) ? 1.f : 0.f;
        d.y = (c.y != 0.f) ? 1.f : 0.f;
        d.z = (c.z != 0.f) ? 1.f : 0.f;
        d.w = (c.w != 0.f) ? 1.f : 0.f;
        __stcs(&drow[q], d);
        __stcs(&crow[q], c);
    }

    if (blockIdx.x == 0 && threadIdx.x == 0) {
        float bal = 0.0f;
        for (int i = 0; i < BB * EE; i++)
            bal += g_proxy[i] * (float)g_cnt0[i];
        bal = bal * (64.0f / 16.0f) / ((float)NN * (float)NN);
        out[2 * SDISP]     = bal;
        out[2 * SDISP + 1] = g_zsum / (float)NTOK;
    }
}

extern "C" void kernel_launch(void* const* d_in, const int* in_sizes, int n_in,
                              void* d_out, int out_size) {
    const float* x     = (const float*)d_in[0];
    const float* W     = (const float*)d_in[1];
    const float* probs = (const float*)d_in[2];
    float* out = (float*)d_out;

    static bool configured = false;
    if (!configured) {
        configured = true;
        cudaFuncSetAttribute(gating_kernel,
                             cudaFuncAttributeMaxDynamicSharedMemorySize, 65536);
    }

    init_kernel<<<1, 32>>>();
    gating_kernel<<<256, 256, 65536>>>(x, W, probs);
    scan_kernel<<<BB, 256>>>();
    fill_kernel<<<NTOK, 256>>>(out);
}